// round 14
// baseline (speedup 1.0000x reference)
#include <cuda_runtime.h>
#include <cuda_fp16.h>
#include <cstdint>
#include <cstddef>

// Problem constants
#define BB   2
#define NN   2048
#define MM   256
#define CC   1024
#define HH   16
#define HD   64
#define SS   2304   // NN + MM

// q pre-scale: hd^-0.5 * log2(e) -> QK logits in log2 domain
#define QSCALE 0.18033688011112042f
// softmax shift: 8 * log2(e)
#define CSH    11.541560327111707f

// Scratch (device globals; fp16 activations)
__device__ __half g_q [(size_t)BB * HH * NN * HD];   // [B,H,N,hd] (rms-normed, xQSCALE)
__device__ __half g_k [(size_t)BB * HH * SS * HD];   // [B,H,S,hd] (rms-normed)
__device__ __half g_v [(size_t)BB * HH * SS * HD];   // [B,H,S,hd]
__device__ __half g_ao[(size_t)BB * NN * CC];        // [B,N,C] attn out
// fp16-preconverted inputs
__device__ __half g_xh  [(size_t)BB * NN * CC];
__device__ __half g_yh  [(size_t)BB * MM * CC];
__device__ __half g_wqkv[(size_t)3 * CC * CC];
__device__ __half g_wkv [(size_t)2 * CC * CC];
__device__ __half g_wp  [(size_t)CC * CC];

// ---------------------------------------------------------------------------
// helpers
// ---------------------------------------------------------------------------
__device__ __forceinline__ uint32_t smem_u32(const void* p) {
    uint32_t a;
    asm("{ .reg .u64 t; cvta.to.shared.u64 t, %1; cvt.u32.u64 %0, t; }"
        : "=r"(a) : "l"(p));
    return a;
}

// m16n8k16 fp16 mma, fp32 accumulate
__device__ __forceinline__ void mma_h(float* c, uint32_t a0, uint32_t a1,
                                      uint32_t a2, uint32_t a3,
                                      uint32_t b0, uint32_t b1) {
    asm volatile(
        "mma.sync.aligned.m16n8k16.row.col.f32.f16.f16.f32 "
        "{%0,%1,%2,%3}, {%4,%5,%6,%7}, {%8,%9}, {%0,%1,%2,%3};"
        : "+f"(c[0]), "+f"(c[1]), "+f"(c[2]), "+f"(c[3])
        : "r"(a0), "r"(a1), "r"(a2), "r"(a3), "r"(b0), "r"(b1));
}

__device__ __forceinline__ uint32_t pack_h2(float x, float y) {
    __half2 h = __floats2half2_rn(x, y);
    return *reinterpret_cast<uint32_t*>(&h);
}

__device__ __forceinline__ float ex2f(float x) {
    float r;
    asm("ex2.approx.f32 %0, %1;" : "=f"(r) : "f"(x));
    return r;
}

#define LDSM4(r0, r1, r2, r3, addr)                                           \
    asm volatile("ldmatrix.sync.aligned.m8n8.x4.shared.b16 {%0,%1,%2,%3}, [%4];" \
                 : "=r"(r0), "=r"(r1), "=r"(r2), "=r"(r3) : "r"(addr))
#define LDSM4T(r0, r1, r2, r3, addr)                                          \
    asm volatile("ldmatrix.sync.aligned.m8n8.x4.trans.shared.b16 {%0,%1,%2,%3}, [%4];" \
                 : "=r"(r0), "=r"(r1), "=r"(r2), "=r"(r3) : "r"(addr))

#define CP16(smem_addr, gptr)                                                 \
    asm volatile("cp.async.cg.shared.global [%0], [%1], 16;"                  \
                 :: "r"(smem_addr), "l"(gptr) : "memory")
#define CP_COMMIT() asm volatile("cp.async.commit_group;" ::: "memory")
#define CP_WAIT1()  asm volatile("cp.async.wait_group 1;"  ::: "memory")

// ---------------------------------------------------------------------------
// merged fp32 -> fp16 pre-convert, one launch, 8 floats/thread.
// ---------------------------------------------------------------------------
#define XB  ((BB * NN * CC) / 2048)        // 2048
#define YB  ((BB * MM * CC) / 2048)        // 256
#define W3B ((3 * CC * CC) / 2048)         // 1536
#define W2B ((2 * CC * CC) / 2048)         // 1024
#define W1B ((CC * CC) / 2048)             // 512
#define CVT_BLOCKS (XB + YB + W3B + W2B + W1B)

__global__ __launch_bounds__(256) void cvt_all(const float* __restrict__ x,
                                               const float* __restrict__ y,
                                               const float* __restrict__ wqkv,
                                               const float* __restrict__ wkv,
                                               const float* __restrict__ wp)
{
    int blk = blockIdx.x;
    const float* src;
    __half* dst;
    if (blk < XB)                    { src = x;    dst = g_xh; }
    else if ((blk -= XB) < YB)       { src = y;    dst = g_yh; }
    else if ((blk -= YB) < W3B)      { src = wqkv; dst = g_wqkv; }
    else if ((blk -= W3B) < W2B)     { src = wkv;  dst = g_wkv; }
    else                             { blk -= W2B; src = wp; dst = g_wp; }
    const size_t i = ((size_t)blk * 256 + threadIdx.x) * 8;
    float4 v0 = *(const float4*)(src + i);
    float4 v1 = *(const float4*)(src + i + 4);
    uint4 u;
    u.x = pack_h2(v0.x, v0.y);
    u.y = pack_h2(v0.z, v0.w);
    u.z = pack_h2(v1.x, v1.y);
    u.w = pack_h2(v1.z, v1.w);
    *(uint4*)(dst + i) = u;
}

// ---------------------------------------------------------------------------
// fp16 NT GEMM, 256x128 CTA tile, warp grid 4x2 (warp tile 64x64), K-chunk 64,
// 3-stage cp.async, m16n8k16 mma. 1 CTA/SM, 128 accum floats/thread.
// Cross-warp fragment redundancy: A x2, B x4 (was A x4, B x2 on 128x128/2x4)
// -> per-MAC smem traffic down 33%.
// PROJ=false: merged QKV (grid y 0..15) + KV (y 16..17) with fused RMSNorm
//             (head = 64 cols = exactly one warp -> norm fully warp-local).
// PROJ=true : output projection from g_ao, fp32 result + bias.
// ---------------------------------------------------------------------------
#define GSTR 72
#define GSTA (256 * GSTR)                  // A halves per stage
#define GSTB (128 * GSTR)                  // B halves per stage
#define GSTAGE (GSTA + GSTB)
#define GEMM_SMEM (3 * GSTAGE * 2)         // 165888 bytes

template <bool PROJ>
__global__ __launch_bounds__(256, 1) void gemm_mma(const float* __restrict__ biasA,
                                                   const float* __restrict__ biasB,
                                                   const float* __restrict__ qn,
                                                   const float* __restrict__ kn,
                                                   float* __restrict__ outp)
{
    extern __shared__ __half smh[];
    const uint32_t sbase = smem_u32(smh);

    const int tid  = threadIdx.x;
    const int lane = tid & 31;
    const int wid  = tid >> 5;
    const int wm   = wid >> 1;          // 0..3 (64-row quarter)
    const int wn   = wid & 1;           // 0..1 (64-col half)
    const int gid  = lane >> 2;
    const int tig  = lane & 3;

    const int colBase = blockIdx.x * 128;
    int mode, rowBase;
    const __half *Aptr, *Wptr;
    const float* bias;
    if (PROJ) {
        mode = 2; rowBase = blockIdx.y * 256;
        Aptr = g_ao; Wptr = g_wp; bias = biasA;
    } else {
        const bool m1 = blockIdx.y >= 16;
        if (m1 && blockIdx.x >= 16) return;     // KV proj has only 16 col-blocks
        mode = m1 ? 1 : 0;
        rowBase = (m1 ? (blockIdx.y - 16) : blockIdx.y) * 256;
        Aptr = m1 ? g_yh : g_xh;
        Wptr = m1 ? g_wkv : g_wqkv;
        bias = m1 ? biasB : biasA;
    }

    const int u_row = tid >> 1;          // 0..127
    const int u_s4  = (tid & 1) * 4;

    auto issue_stage = [&](int stage, int k0) {
        const uint32_t aOff = sbase + (uint32_t)(stage * GSTAGE) * 2;
        const uint32_t bOff = aOff + (uint32_t)GSTA * 2;
#pragma unroll
        for (int i = 0; i < 4; i++) {
            const int seg = u_s4 + i;
            // A: rows u_row and u_row+128
            CP16(aOff + (uint32_t)(u_row * GSTR + seg * 8) * 2,
                 Aptr + (size_t)(rowBase + u_row) * CC + k0 + seg * 8);
            CP16(aOff + (uint32_t)((u_row + 128) * GSTR + seg * 8) * 2,
                 Aptr + (size_t)(rowBase + u_row + 128) * CC + k0 + seg * 8);
            // B: row u_row
            CP16(bOff + (uint32_t)(u_row * GSTR + seg * 8) * 2,
                 Wptr + (size_t)(colBase + u_row) * CC + k0 + seg * 8);
        }
        CP_COMMIT();
    };

    float c[4][8][4];
#pragma unroll
    for (int mt = 0; mt < 4; mt++)
#pragma unroll
        for (int nt = 0; nt < 8; nt++)
#pragma unroll
            for (int q = 0; q < 4; q++) c[mt][nt][q] = 0.f;

    issue_stage(0, 0);
    issue_stage(1, 64);

    const int lr8  = lane & 7;
    const int aRow = (lane >> 3) & 1;
    const int aCol = lane >> 4;

    for (int chunk = 0; chunk < 16; ++chunk) {
        CP_WAIT1();
        __syncthreads();

        if (chunk + 2 < 16) issue_stage((chunk + 2) % 3, (chunk + 2) * 64);
        else CP_COMMIT();

        const int st = chunk % 3;
        const uint32_t aB = sbase + (uint32_t)(st * GSTAGE) * 2;
        const uint32_t bB = aB + (uint32_t)GSTA * 2;

#pragma unroll
        for (int kk = 0; kk < 4; kk++) {
            uint32_t a[4][4];
#pragma unroll
            for (int mt = 0; mt < 4; mt++)
                LDSM4(a[mt][0], a[mt][1], a[mt][2], a[mt][3],
                      aB + (uint32_t)((wm * 64 + mt * 16 + lr8 + aRow * 8) * GSTR
                                      + kk * 16 + aCol * 8) * 2);
#pragma unroll
            for (int p = 0; p < 4; p++) {
                uint32_t b0, b1, b2, b3;
                LDSM4(b0, b1, b2, b3,
                      bB + (uint32_t)((wn * 64 + p * 16 + lr8 + aCol * 8) * GSTR
                                      + kk * 16 + aRow * 8) * 2);
#pragma unroll
                for (int mt = 0; mt < 4; mt++) {
                    mma_h(c[mt][2 * p],     a[mt][0], a[mt][1], a[mt][2], a[mt][3], b0, b1);
                    mma_h(c[mt][2 * p + 1], a[mt][0], a[mt][1], a[mt][2], a[mt][3], b2, b3);
                }
            }
        }
    }

    // ---- epilogue: bias (fp32) ----
#pragma unroll
    for (int nt = 0; nt < 8; nt++) {
        const float2 bv = *(const float2*)&bias[colBase + wn * 64 + nt * 8 + tig * 2];
#pragma unroll
        for (int mt = 0; mt < 4; mt++) {
            c[mt][nt][0] += bv.x; c[mt][nt][1] += bv.y;
            c[mt][nt][2] += bv.x; c[mt][nt][3] += bv.y;
        }
    }

    // ---- fused RMSNorm (q/k segments), warp-local: head = this warp's 64 cols
    if (!PROJ) {
        const int seg = colBase >> 10;               // uniform per block
        const bool donorm = (mode == 0) ? (seg <= 1) : (seg == 0);
        if (donorm) {
            const float* w = (mode == 0 && seg == 0) ? qn : kn;
            const float sc = (mode == 0 && seg == 0) ? QSCALE : 1.0f;
            float2 wv[8];
#pragma unroll
            for (int nt = 0; nt < 8; nt++)
                wv[nt] = *(const float2*)&w[nt * 8 + tig * 2];
#pragma unroll
            for (int mt = 0; mt < 4; mt++)
#pragma unroll
                for (int hf = 0; hf < 2; hf++) {
                    float s = 0.f;
#pragma unroll
                    for (int nt = 0; nt < 8; nt++) {
                        const float x0 = c[mt][nt][hf * 2 + 0];
                        const float x1 = c[mt][nt][hf * 2 + 1];
                        s += x0 * x0 + x1 * x1;
                    }
                    s += __shfl_xor_sync(0xffffffffu, s, 1);
                    s += __shfl_xor_sync(0xffffffffu, s, 2);
                    const float inv = rsqrtf(s * (1.0f / 64.0f) + 1e-6f) * sc;
#pragma unroll
                    for (int nt = 0; nt < 8; nt++) {
                        c[mt][nt][hf * 2 + 0] *= inv * wv[nt].x;
                        c[mt][nt][hf * 2 + 1] *= inv * wv[nt].y;
                    }
                }
        }
    }

    // ---- scatter ----
#pragma unroll
    for (int mt = 0; mt < 4; mt++)
#pragma unroll
        for (int nt = 0; nt < 8; nt++)
#pragma unroll
            for (int hf = 0; hf < 2; hf++) {
                const int row = rowBase + wm * 64 + mt * 16 + gid + hf * 8;
                const int col = colBase + wn * 64 + nt * 8 + tig * 2;
                const float vx = c[mt][nt][hf * 2 + 0];
                const float vy = c[mt][nt][hf * 2 + 1];
                if (PROJ) {
                    float2 v; v.x = vx; v.y = vy;
                    *(float2*)(outp + (size_t)row * CC + col) = v;
                } else {
                    __half* dst;
                    if (mode == 0) {
                        const int b_ = row >> 11, n = row & (NN - 1);
                        const int t3 = col >> 10, h = (col >> 6) & 15, d = col & 63;
                        const size_t bh = (size_t)b_ * HH + h;
                        if (t3 == 0)      dst = g_q + (bh * NN + n) * HD + d;
                        else if (t3 == 1) dst = g_k + (bh * SS + n) * HD + d;
                        else              dst = g_v + (bh * SS + n) * HD + d;
                    } else {
                        const int b_ = row >> 8, mm = row & (MM - 1);
                        const int t2 = col >> 10, h = (col >> 6) & 15, d = col & 63;
                        const size_t bh = (size_t)b_ * HH + h;
                        dst = (t2 == 0) ? g_k + (bh * SS + NN + mm) * HD + d
                                        : g_v + (bh * SS + NN + mm) * HD + d;
                    }
                    *(__half2*)dst = __floats2half2_rn(vx, vy);
                }
            }
}

// ---------------------------------------------------------------------------
// fp16 flash attention; Q and P in registers; fp32 ex2 softmax; l on fma pipe.
// CTA: 128 queries x (b,h); 8 warps; S-chunks of 64 (36 iters).
// smem: 3 stages x (K[64][72] + V[64][72]) halves = 55296 B.
// ---------------------------------------------------------------------------
#define ASTR 72
#define KVSTG (2 * 64 * ASTR)              // halves per stage (K+V)
#define ATTN_SMEM (3 * KVSTG * 2)          // 55296 bytes

__global__ __launch_bounds__(256, 2) void attn_mma()
{
    extern __shared__ __half sh[];
    const uint32_t sbase = smem_u32(sh);

    const int tid  = threadIdx.x;
    const int lane = tid & 31;
    const int wid  = tid >> 5;
    const int gid  = lane >> 2;
    const int tig  = lane & 3;
    const int lr8  = lane & 7;
    const int aRow = (lane >> 3) & 1;
    const int aCol = lane >> 4;

    const int qb = blockIdx.x * 128;
    const int h  = blockIdx.y;
    const int b  = blockIdx.z;
    const size_t bh = (size_t)b * HH + h;

    const __half* qg = g_q + (bh * NN + qb) * HD;
    const __half* kg = g_k + bh * SS * HD;
    const __half* vg = g_v + bh * SS * HD;

    const int kv_row = tid >> 2;
    const int kv_sg  = tid & 3;
    auto issue_stage = [&](int stage, int sc) {
        const uint32_t kOff = sbase + (uint32_t)(stage * KVSTG) * 2;
        const uint32_t vOff = kOff + 64 * ASTR * 2;
#pragma unroll
        for (int i = 0; i < 2; i++) {
            const int seg = kv_sg * 2 + i;
            const uint32_t d = (uint32_t)(kv_row * ASTR + seg * 8) * 2;
            CP16(kOff + d, kg + (size_t)(sc + kv_row) * HD + seg * 8);
            CP16(vOff + d, vg + (size_t)(sc + kv_row) * HD + seg * 8);
        }
        CP_COMMIT();
    };

    issue_stage(0, 0);
    issue_stage(1, 64);

    // stage Q through the stage-2 region, pull into fragments
    const int wrow = wid * 16;
    uint32_t qf[4][4];
    {
        __half* qsm = sh + 2 * KVSTG;
#pragma unroll
        for (int i = 0; i < 4; i++) {
            const int u = tid + 256 * i;
            const int row = u >> 3, seg = u & 7;
            *(uint4*)&qsm[row * ASTR + seg * 8] =
                *(const uint4*)&qg[(size_t)row * HD + seg * 8];
        }
        __syncthreads();
        const uint32_t qB = sbase + (uint32_t)(2 * KVSTG) * 2;
#pragma unroll
        for (int kk = 0; kk < 4; kk++)
            LDSM4(qf[kk][0], qf[kk][1], qf[kk][2], qf[kk][3],
                  qB + (uint32_t)((wrow + lr8 + aRow * 8) * ASTR
                                  + kk * 16 + aCol * 8) * 2);
        __syncthreads();
    }

    float oacc[8][4];
#pragma unroll
    for (int nt = 0; nt < 8; nt++)
#pragma unroll
        for (int q = 0; q < 4; q++) oacc[nt][q] = 0.f;
    float l0 = 0.f, l1 = 0.f;

    for (int c = 0; c < 36; ++c) {
        CP_WAIT1();
        __syncthreads();

        if (c + 2 < 36) issue_stage((c + 2) % 3, (c + 2) * 64);
        else CP_COMMIT();

        const int st = c % 3;
        const uint32_t ksB = sbase + (uint32_t)(st * KVSTG) * 2;
        const uint32_t vsB = ksB + 64 * ASTR * 2;

        // ---- S = Q @ K^T - CSH (shift folded into init) ----
        float s[8][4];
#pragma unroll
        for (int nt = 0; nt < 8; nt++)
#pragma unroll
            for (int q = 0; q < 4; q++) s[nt][q] = -CSH;

#pragma unroll
        for (int kk = 0; kk < 4; kk++) {
#pragma unroll
            for (int p = 0; p < 4; p++) {
                uint32_t b0, b1, b2, b3;
                LDSM4(b0, b1, b2, b3,
                      ksB + (uint32_t)((p * 16 + lr8 + aCol * 8) * ASTR
                                       + kk * 16 + aRow * 8) * 2);
                mma_h(s[2 * p],     qf[kk][0], qf[kk][1], qf[kk][2], qf[kk][3], b0, b1);
                mma_h(s[2 * p + 1], qf[kk][0], qf[kk][1], qf[kk][2], qf[kk][3], b2, b3);
            }
        }

        // ---- softmax: p = 2^S via fp32 ex2; l summed on fma pipe ----
        uint32_t hlo[8], hhi[8];
        float rs0 = 0.f, rs1 = 0.f;
#pragma unroll
        for (int nt = 0; nt < 8; nt++) {
            const float p00 = ex2f(s[nt][0]);
            const float p01 = ex2f(s[nt][1]);
            const float p10 = ex2f(s[nt][2]);
            const float p11 = ex2f(s[nt][3]);
            rs0 += p00 + p01;
            rs1 += p10 + p11;
            hlo[nt] = pack_h2(p00, p01);
            hhi[nt] = pack_h2(p10, p11);
        }
        l0 += rs0;
        l1 += rs1;

        // ---- O += P @ V ----
#pragma unroll
        for (int kk = 0; kk < 4; kk++) {
            const uint32_t a0 = hlo[2 * kk],     a1 = hhi[2 * kk];
            const uint32_t a2 = hlo[2 * kk + 1], a3 = hhi[2 * kk + 1];
#pragma unroll
            for (int p = 0; p < 4; p++) {
                uint32_t b0, b1, b2, b3;
                LDSM4T(b0, b1, b2, b3,
                       vsB + (uint32_t)((kk * 16 + lr8 + aRow * 8) * ASTR
                                        + p * 16 + aCol * 8) * 2);
                mma_h(oacc[2 * p],     a0, a1, a2, a3, b0, b1);
                mma_h(oacc[2 * p + 1], a0, a1, a2, a3, b2, b3);
            }
        }
    }

    // ---- epilogue: quad-reduce l, normalize, write fp16 ----
    l0 += __shfl_xor_sync(0xffffffffu, l0, 1);
    l0 += __shfl_xor_sync(0xffffffffu, l0, 2);
    l1 += __shfl_xor_sync(0xffffffffu, l1, 1);
    l1 += __shfl_xor_sync(0xffffffffu, l1, 2);
    const float inv0 = 1.0f / l0;
    const float inv1 = 1.0f / l1;
    const int n0 = qb + wrow + gid;
    const int n1 = n0 + 8;
#pragma unroll
    for (int nt = 0; nt < 8; nt++) {
        const int d = h * HD + nt * 8 + tig * 2;
        *(__half2*)&g_ao[((size_t)b * NN + n0) * CC + d] =
            __floats2half2_rn(oacc[nt][0] * inv0, oacc[nt][1] * inv0);
        *(__half2*)&g_ao[((size_t)b * NN + n1) * CC + d] =
            __floats2half2_rn(oacc[nt][2] * inv1, oacc[nt][3] * inv1);
    }
}

// ---------------------------------------------------------------------------
extern "C" void kernel_launch(void* const* d_in, const int* in_sizes, int n_in,
                              void* d_out, int out_size)
{
    const float* x      = (const float*)d_in[0];
    const float* y      = (const float*)d_in[1];
    const float* qkv_w  = (const float*)d_in[2];
    const float* qkv_b  = (const float*)d_in[3];
    const float* kv_w   = (const float*)d_in[4];
    const float* kv_b   = (const float*)d_in[5];
    const float* qn_w   = (const float*)d_in[6];
    const float* kn_w   = (const float*)d_in[7];
    const float* proj_w = (const float*)d_in[8];
    const float* proj_b = (const float*)d_in[9];
    float* out = (float*)d_out;

    (void)in_sizes; (void)n_in; (void)out_size;

    cudaFuncSetAttribute(gemm_mma<false>, cudaFuncAttributeMaxDynamicSharedMemorySize, GEMM_SMEM);
    cudaFuncSetAttribute(gemm_mma<true>,  cudaFuncAttributeMaxDynamicSharedMemorySize, GEMM_SMEM);
    cudaFuncSetAttribute(attn_mma, cudaFuncAttributeMaxDynamicSharedMemorySize, ATTN_SMEM);

    // 1) merged fp32->fp16 conversion pass (8 floats/thread)
    cvt_all<<<CVT_BLOCKS, 256>>>(x, y, qkv_w, kv_w, proj_w);

    // 2) merged QKV (y 0..15) + KV (y 16..17) projections, fused RMSNorm
    gemm_mma<false><<<dim3(24, 18), 256, GEMM_SMEM>>>(qkv_b, kv_b, qn_w, kn_w, nullptr);

    // 3) attention
    attn_mma<<<dim3(NN / 128, HH, BB), 256, ATTN_SMEM>>>();

    // 4) output projection -> d_out
    gemm_mma<true><<<dim3(8, 16), 256, GEMM_SMEM>>>(proj_b, nullptr, nullptr, nullptr, out);
}

// round 16
// speedup vs baseline: 1.0074x; 1.0074x over previous
#include <cuda_runtime.h>
#include <cuda_fp16.h>
#include <cstdint>
#include <cstddef>

// Problem constants
#define BB   2
#define NN   2048
#define MM   256
#define CC   1024
#define HH   16
#define HD   64
#define SS   2304   // NN + MM

// q pre-scale: hd^-0.5 * log2(e) -> QK logits in log2 domain
#define QSCALE 0.18033688011112042f
// softmax shift: 8 * log2(e)
#define CSH    11.541560327111707f

// Scratch (device globals; fp16 activations)
__device__ __half g_q [(size_t)BB * HH * NN * HD];   // [B,H,N,hd] (rms-normed, xQSCALE)
__device__ __half g_k [(size_t)BB * HH * SS * HD];   // [B,H,S,hd] (rms-normed)
__device__ __half g_v [(size_t)BB * HH * SS * HD];   // [B,H,S,hd]
__device__ __half g_ao[(size_t)BB * NN * CC];        // [B,N,C] attn out
// fp16-preconverted inputs
__device__ __half g_xh  [(size_t)BB * NN * CC];
__device__ __half g_yh  [(size_t)BB * MM * CC];
__device__ __half g_wqkv[(size_t)3 * CC * CC];
__device__ __half g_wkv [(size_t)2 * CC * CC];
__device__ __half g_wp  [(size_t)CC * CC];

// ---------------------------------------------------------------------------
// helpers
// ---------------------------------------------------------------------------
__device__ __forceinline__ uint32_t smem_u32(const void* p) {
    uint32_t a;
    asm("{ .reg .u64 t; cvta.to.shared.u64 t, %1; cvt.u32.u64 %0, t; }"
        : "=r"(a) : "l"(p));
    return a;
}

// m16n8k16 fp16 mma, fp32 accumulate
__device__ __forceinline__ void mma_h(float* c, uint32_t a0, uint32_t a1,
                                      uint32_t a2, uint32_t a3,
                                      uint32_t b0, uint32_t b1) {
    asm volatile(
        "mma.sync.aligned.m16n8k16.row.col.f32.f16.f16.f32 "
        "{%0,%1,%2,%3}, {%4,%5,%6,%7}, {%8,%9}, {%0,%1,%2,%3};"
        : "+f"(c[0]), "+f"(c[1]), "+f"(c[2]), "+f"(c[3])
        : "r"(a0), "r"(a1), "r"(a2), "r"(a3), "r"(b0), "r"(b1));
}

__device__ __forceinline__ uint32_t pack_h2(float x, float y) {
    __half2 h = __floats2half2_rn(x, y);
    return *reinterpret_cast<uint32_t*>(&h);
}

__device__ __forceinline__ float ex2f(float x) {
    float r;
    asm("ex2.approx.f32 %0, %1;" : "=f"(r) : "f"(x));
    return r;
}

#define LDSM4(r0, r1, r2, r3, addr)                                           \
    asm volatile("ldmatrix.sync.aligned.m8n8.x4.shared.b16 {%0,%1,%2,%3}, [%4];" \
                 : "=r"(r0), "=r"(r1), "=r"(r2), "=r"(r3) : "r"(addr))
#define LDSM4T(r0, r1, r2, r3, addr)                                          \
    asm volatile("ldmatrix.sync.aligned.m8n8.x4.trans.shared.b16 {%0,%1,%2,%3}, [%4];" \
                 : "=r"(r0), "=r"(r1), "=r"(r2), "=r"(r3) : "r"(addr))

#define CP16(smem_addr, gptr)                                                 \
    asm volatile("cp.async.cg.shared.global [%0], [%1], 16;"                  \
                 :: "r"(smem_addr), "l"(gptr) : "memory")
#define CP_COMMIT() asm volatile("cp.async.commit_group;" ::: "memory")
#define CP_WAIT1()  asm volatile("cp.async.wait_group 1;"  ::: "memory")

// ---------------------------------------------------------------------------
// merged fp32 -> fp16 pre-convert, one launch, 8 floats/thread.
// ---------------------------------------------------------------------------
#define XB  ((BB * NN * CC) / 2048)        // 2048
#define YB  ((BB * MM * CC) / 2048)        // 256
#define W3B ((3 * CC * CC) / 2048)         // 1536
#define W2B ((2 * CC * CC) / 2048)         // 1024
#define W1B ((CC * CC) / 2048)             // 512
#define CVT_BLOCKS (XB + YB + W3B + W2B + W1B)

__global__ __launch_bounds__(256) void cvt_all(const float* __restrict__ x,
                                               const float* __restrict__ y,
                                               const float* __restrict__ wqkv,
                                               const float* __restrict__ wkv,
                                               const float* __restrict__ wp)
{
    int blk = blockIdx.x;
    const float* src;
    __half* dst;
    if (blk < XB)                    { src = x;    dst = g_xh; }
    else if ((blk -= XB) < YB)       { src = y;    dst = g_yh; }
    else if ((blk -= YB) < W3B)      { src = wqkv; dst = g_wqkv; }
    else if ((blk -= W3B) < W2B)     { src = wkv;  dst = g_wkv; }
    else                             { blk -= W2B; src = wp; dst = g_wp; }
    const size_t i = ((size_t)blk * 256 + threadIdx.x) * 8;
    float4 v0 = *(const float4*)(src + i);
    float4 v1 = *(const float4*)(src + i + 4);
    uint4 u;
    u.x = pack_h2(v0.x, v0.y);
    u.y = pack_h2(v0.z, v0.w);
    u.z = pack_h2(v1.x, v1.y);
    u.w = pack_h2(v1.z, v1.w);
    *(uint4*)(dst + i) = u;
}

// ---------------------------------------------------------------------------
// fp16 NT GEMM, 256x128 CTA tile, warp grid 4x2 (warp tile 64x64), K-chunk 64,
// 3-stage cp.async, m16n8k16 mma. (R14 config, measured best for gemm<1>.)
// PROJ=false: merged QKV (grid y 0..15) + KV (y 16..17) with fused RMSNorm.
// PROJ=true : output projection from g_ao, fp32 result + bias.
// ---------------------------------------------------------------------------
#define GSTR 72
#define GSTA (256 * GSTR)                  // A halves per stage
#define GSTB (128 * GSTR)                  // B halves per stage
#define GSTAGE (GSTA + GSTB)
#define GEMM_SMEM (3 * GSTAGE * 2)         // 165888 bytes

template <bool PROJ>
__global__ __launch_bounds__(256, 1) void gemm_mma(const float* __restrict__ biasA,
                                                   const float* __restrict__ biasB,
                                                   const float* __restrict__ qn,
                                                   const float* __restrict__ kn,
                                                   float* __restrict__ outp)
{
    extern __shared__ __half smh[];
    const uint32_t sbase = smem_u32(smh);

    const int tid  = threadIdx.x;
    const int lane = tid & 31;
    const int wid  = tid >> 5;
    const int wm   = wid >> 1;          // 0..3 (64-row quarter)
    const int wn   = wid & 1;           // 0..1 (64-col half)
    const int gid  = lane >> 2;
    const int tig  = lane & 3;

    const int colBase = blockIdx.x * 128;
    int mode, rowBase;
    const __half *Aptr, *Wptr;
    const float* bias;
    if (PROJ) {
        mode = 2; rowBase = blockIdx.y * 256;
        Aptr = g_ao; Wptr = g_wp; bias = biasA;
    } else {
        const bool m1 = blockIdx.y >= 16;
        if (m1 && blockIdx.x >= 16) return;     // KV proj has only 16 col-blocks
        mode = m1 ? 1 : 0;
        rowBase = (m1 ? (blockIdx.y - 16) : blockIdx.y) * 256;
        Aptr = m1 ? g_yh : g_xh;
        Wptr = m1 ? g_wkv : g_wqkv;
        bias = m1 ? biasB : biasA;
    }

    const int u_row = tid >> 1;          // 0..127
    const int u_s4  = (tid & 1) * 4;

    auto issue_stage = [&](int stage, int k0) {
        const uint32_t aOff = sbase + (uint32_t)(stage * GSTAGE) * 2;
        const uint32_t bOff = aOff + (uint32_t)GSTA * 2;
#pragma unroll
        for (int i = 0; i < 4; i++) {
            const int seg = u_s4 + i;
            CP16(aOff + (uint32_t)(u_row * GSTR + seg * 8) * 2,
                 Aptr + (size_t)(rowBase + u_row) * CC + k0 + seg * 8);
            CP16(aOff + (uint32_t)((u_row + 128) * GSTR + seg * 8) * 2,
                 Aptr + (size_t)(rowBase + u_row + 128) * CC + k0 + seg * 8);
            CP16(bOff + (uint32_t)(u_row * GSTR + seg * 8) * 2,
                 Wptr + (size_t)(colBase + u_row) * CC + k0 + seg * 8);
        }
        CP_COMMIT();
    };

    float c[4][8][4];
#pragma unroll
    for (int mt = 0; mt < 4; mt++)
#pragma unroll
        for (int nt = 0; nt < 8; nt++)
#pragma unroll
            for (int q = 0; q < 4; q++) c[mt][nt][q] = 0.f;

    issue_stage(0, 0);
    issue_stage(1, 64);

    const int lr8  = lane & 7;
    const int aRow = (lane >> 3) & 1;
    const int aCol = lane >> 4;

    for (int chunk = 0; chunk < 16; ++chunk) {
        CP_WAIT1();
        __syncthreads();

        if (chunk + 2 < 16) issue_stage((chunk + 2) % 3, (chunk + 2) * 64);
        else CP_COMMIT();

        const int st = chunk % 3;
        const uint32_t aB = sbase + (uint32_t)(st * GSTAGE) * 2;
        const uint32_t bB = aB + (uint32_t)GSTA * 2;

#pragma unroll
        for (int kk = 0; kk < 4; kk++) {
            uint32_t a[4][4];
#pragma unroll
            for (int mt = 0; mt < 4; mt++)
                LDSM4(a[mt][0], a[mt][1], a[mt][2], a[mt][3],
                      aB + (uint32_t)((wm * 64 + mt * 16 + lr8 + aRow * 8) * GSTR
                                      + kk * 16 + aCol * 8) * 2);
#pragma unroll
            for (int p = 0; p < 4; p++) {
                uint32_t b0, b1, b2, b3;
                LDSM4(b0, b1, b2, b3,
                      bB + (uint32_t)((wn * 64 + p * 16 + lr8 + aCol * 8) * GSTR
                                      + kk * 16 + aRow * 8) * 2);
#pragma unroll
                for (int mt = 0; mt < 4; mt++) {
                    mma_h(c[mt][2 * p],     a[mt][0], a[mt][1], a[mt][2], a[mt][3], b0, b1);
                    mma_h(c[mt][2 * p + 1], a[mt][0], a[mt][1], a[mt][2], a[mt][3], b2, b3);
                }
            }
        }
    }

    // ---- epilogue: bias (fp32) ----
#pragma unroll
    for (int nt = 0; nt < 8; nt++) {
        const float2 bv = *(const float2*)&bias[colBase + wn * 64 + nt * 8 + tig * 2];
#pragma unroll
        for (int mt = 0; mt < 4; mt++) {
            c[mt][nt][0] += bv.x; c[mt][nt][1] += bv.y;
            c[mt][nt][2] += bv.x; c[mt][nt][3] += bv.y;
        }
    }

    // ---- fused RMSNorm (q/k segments), warp-local: head = this warp's 64 cols
    if (!PROJ) {
        const int seg = colBase >> 10;               // uniform per block
        const bool donorm = (mode == 0) ? (seg <= 1) : (seg == 0);
        if (donorm) {
            const float* w = (mode == 0 && seg == 0) ? qn : kn;
            const float sc = (mode == 0 && seg == 0) ? QSCALE : 1.0f;
            float2 wv[8];
#pragma unroll
            for (int nt = 0; nt < 8; nt++)
                wv[nt] = *(const float2*)&w[nt * 8 + tig * 2];
#pragma unroll
            for (int mt = 0; mt < 4; mt++)
#pragma unroll
                for (int hf = 0; hf < 2; hf++) {
                    float s = 0.f;
#pragma unroll
                    for (int nt = 0; nt < 8; nt++) {
                        const float x0 = c[mt][nt][hf * 2 + 0];
                        const float x1 = c[mt][nt][hf * 2 + 1];
                        s += x0 * x0 + x1 * x1;
                    }
                    s += __shfl_xor_sync(0xffffffffu, s, 1);
                    s += __shfl_xor_sync(0xffffffffu, s, 2);
                    const float inv = rsqrtf(s * (1.0f / 64.0f) + 1e-6f) * sc;
#pragma unroll
                    for (int nt = 0; nt < 8; nt++) {
                        c[mt][nt][hf * 2 + 0] *= inv * wv[nt].x;
                        c[mt][nt][hf * 2 + 1] *= inv * wv[nt].y;
                    }
                }
        }
    }

    // ---- scatter ----
#pragma unroll
    for (int mt = 0; mt < 4; mt++)
#pragma unroll
        for (int nt = 0; nt < 8; nt++)
#pragma unroll
            for (int hf = 0; hf < 2; hf++) {
                const int row = rowBase + wm * 64 + mt * 16 + gid + hf * 8;
                const int col = colBase + wn * 64 + nt * 8 + tig * 2;
                const float vx = c[mt][nt][hf * 2 + 0];
                const float vy = c[mt][nt][hf * 2 + 1];
                if (PROJ) {
                    float2 v; v.x = vx; v.y = vy;
                    *(float2*)(outp + (size_t)row * CC + col) = v;
                } else {
                    __half* dst;
                    if (mode == 0) {
                        const int b_ = row >> 11, n = row & (NN - 1);
                        const int t3 = col >> 10, h = (col >> 6) & 15, d = col & 63;
                        const size_t bh = (size_t)b_ * HH + h;
                        if (t3 == 0)      dst = g_q + (bh * NN + n) * HD + d;
                        else if (t3 == 1) dst = g_k + (bh * SS + n) * HD + d;
                        else              dst = g_v + (bh * SS + n) * HD + d;
                    } else {
                        const int b_ = row >> 8, mm = row & (MM - 1);
                        const int t2 = col >> 10, h = (col >> 6) & 15, d = col & 63;
                        const size_t bh = (size_t)b_ * HH + h;
                        dst = (t2 == 0) ? g_k + (bh * SS + NN + mm) * HD + d
                                        : g_v + (bh * SS + NN + mm) * HD + d;
                    }
                    *(__half2*)dst = __floats2half2_rn(vx, vy);
                }
            }
}

// ---------------------------------------------------------------------------
// fp16 flash attention; Q and P in registers; fp32 ex2 softmax; l on fma pipe.
// Softmax and PV interleaved per key-group kk (PV kk needs only S-tiles
// 2kk, 2kk+1) to break the per-chunk MUFU/tensor phase bursts.
// CTA: 128 queries x (b,h); 8 warps; S-chunks of 64 (36 iters).
// smem: 3 stages x (K[64][72] + V[64][72]) halves = 55296 B.
// ---------------------------------------------------------------------------
#define ASTR 72
#define KVSTG (2 * 64 * ASTR)              // halves per stage (K+V)
#define ATTN_SMEM (3 * KVSTG * 2)          // 55296 bytes

__global__ __launch_bounds__(256, 2) void attn_mma()
{
    extern __shared__ __half sh[];
    const uint32_t sbase = smem_u32(sh);

    const int tid  = threadIdx.x;
    const int lane = tid & 31;
    const int wid  = tid >> 5;
    const int gid  = lane >> 2;
    const int tig  = lane & 3;
    const int lr8  = lane & 7;
    const int aRow = (lane >> 3) & 1;
    const int aCol = lane >> 4;

    const int qb = blockIdx.x * 128;
    const int h  = blockIdx.y;
    const int b  = blockIdx.z;
    const size_t bh = (size_t)b * HH + h;

    const __half* qg = g_q + (bh * NN + qb) * HD;
    const __half* kg = g_k + bh * SS * HD;
    const __half* vg = g_v + bh * SS * HD;

    const int kv_row = tid >> 2;
    const int kv_sg  = tid & 3;
    auto issue_stage = [&](int stage, int sc) {
        const uint32_t kOff = sbase + (uint32_t)(stage * KVSTG) * 2;
        const uint32_t vOff = kOff + 64 * ASTR * 2;
#pragma unroll
        for (int i = 0; i < 2; i++) {
            const int seg = kv_sg * 2 + i;
            const uint32_t d = (uint32_t)(kv_row * ASTR + seg * 8) * 2;
            CP16(kOff + d, kg + (size_t)(sc + kv_row) * HD + seg * 8);
            CP16(vOff + d, vg + (size_t)(sc + kv_row) * HD + seg * 8);
        }
        CP_COMMIT();
    };

    issue_stage(0, 0);
    issue_stage(1, 64);

    // stage Q through the stage-2 region, pull into fragments
    const int wrow = wid * 16;
    uint32_t qf[4][4];
    {
        __half* qsm = sh + 2 * KVSTG;
#pragma unroll
        for (int i = 0; i < 4; i++) {
            const int u = tid + 256 * i;
            const int row = u >> 3, seg = u & 7;
            *(uint4*)&qsm[row * ASTR + seg * 8] =
                *(const uint4*)&qg[(size_t)row * HD + seg * 8];
        }
        __syncthreads();
        const uint32_t qB = sbase + (uint32_t)(2 * KVSTG) * 2;
#pragma unroll
        for (int kk = 0; kk < 4; kk++)
            LDSM4(qf[kk][0], qf[kk][1], qf[kk][2], qf[kk][3],
                  qB + (uint32_t)((wrow + lr8 + aRow * 8) * ASTR
                                  + kk * 16 + aCol * 8) * 2);
        __syncthreads();
    }

    float oacc[8][4];
#pragma unroll
    for (int nt = 0; nt < 8; nt++)
#pragma unroll
        for (int q = 0; q < 4; q++) oacc[nt][q] = 0.f;
    float l0 = 0.f, l1 = 0.f;

    for (int c = 0; c < 36; ++c) {
        CP_WAIT1();
        __syncthreads();

        if (c + 2 < 36) issue_stage((c + 2) % 3, (c + 2) * 64);
        else CP_COMMIT();

        const int st = c % 3;
        const uint32_t ksB = sbase + (uint32_t)(st * KVSTG) * 2;
        const uint32_t vsB = ksB + 64 * ASTR * 2;

        // ---- S = Q @ K^T - CSH (shift folded into init) ----
        float s[8][4];
#pragma unroll
        for (int nt = 0; nt < 8; nt++)
#pragma unroll
            for (int q = 0; q < 4; q++) s[nt][q] = -CSH;

#pragma unroll
        for (int kk = 0; kk < 4; kk++) {
#pragma unroll
            for (int p = 0; p < 4; p++) {
                uint32_t b0, b1, b2, b3;
                LDSM4(b0, b1, b2, b3,
                      ksB + (uint32_t)((p * 16 + lr8 + aCol * 8) * ASTR
                                       + kk * 16 + aRow * 8) * 2);
                mma_h(s[2 * p],     qf[kk][0], qf[kk][1], qf[kk][2], qf[kk][3], b0, b1);
                mma_h(s[2 * p + 1], qf[kk][0], qf[kk][1], qf[kk][2], qf[kk][3], b2, b3);
            }
        }

        // ---- interleaved softmax + PV per key-group kk ----
#pragma unroll
        for (int kk = 0; kk < 4; kk++) {
            // V fragments first (independent of softmax -> covers MUFU latency)
            uint32_t vb[4][4];
#pragma unroll
            for (int p = 0; p < 4; p++)
                LDSM4T(vb[p][0], vb[p][1], vb[p][2], vb[p][3],
                       vsB + (uint32_t)((kk * 16 + lr8 + aRow * 8) * ASTR
                                        + p * 16 + aCol * 8) * 2);
            // softmax for S-tiles 2kk, 2kk+1 (the only tiles PV-kk needs)
            const float pa0 = ex2f(s[2 * kk][0]);
            const float pa1 = ex2f(s[2 * kk][1]);
            const float pa2 = ex2f(s[2 * kk][2]);
            const float pa3 = ex2f(s[2 * kk][3]);
            const float pb0 = ex2f(s[2 * kk + 1][0]);
            const float pb1 = ex2f(s[2 * kk + 1][1]);
            const float pb2 = ex2f(s[2 * kk + 1][2]);
            const float pb3 = ex2f(s[2 * kk + 1][3]);
            l0 += pa0 + pa1 + pb0 + pb1;
            l1 += pa2 + pa3 + pb2 + pb3;
            const uint32_t a0 = pack_h2(pa0, pa1);
            const uint32_t a1 = pack_h2(pa2, pa3);
            const uint32_t a2 = pack_h2(pb0, pb1);
            const uint32_t a3 = pack_h2(pb2, pb3);
            // PV mma for this key group
#pragma unroll
            for (int p = 0; p < 4; p++) {
                mma_h(oacc[2 * p],     a0, a1, a2, a3, vb[p][0], vb[p][1]);
                mma_h(oacc[2 * p + 1], a0, a1, a2, a3, vb[p][2], vb[p][3]);
            }
        }
    }

    // ---- epilogue: quad-reduce l, normalize, write fp16 ----
    l0 += __shfl_xor_sync(0xffffffffu, l0, 1);
    l0 += __shfl_xor_sync(0xffffffffu, l0, 2);
    l1 += __shfl_xor_sync(0xffffffffu, l1, 1);
    l1 += __shfl_xor_sync(0xffffffffu, l1, 2);
    const float inv0 = 1.0f / l0;
    const float inv1 = 1.0f / l1;
    const int n0 = qb + wrow + gid;
    const int n1 = n0 + 8;
#pragma unroll
    for (int nt = 0; nt < 8; nt++) {
        const int d = h * HD + nt * 8 + tig * 2;
        *(__half2*)&g_ao[((size_t)b * NN + n0) * CC + d] =
            __floats2half2_rn(oacc[nt][0] * inv0, oacc[nt][1] * inv0);
        *(__half2*)&g_ao[((size_t)b * NN + n1) * CC + d] =
            __floats2half2_rn(oacc[nt][2] * inv1, oacc[nt][3] * inv1);
    }
}

// ---------------------------------------------------------------------------
extern "C" void kernel_launch(void* const* d_in, const int* in_sizes, int n_in,
                              void* d_out, int out_size)
{
    const float* x      = (const float*)d_in[0];
    const float* y      = (const float*)d_in[1];
    const float* qkv_w  = (const float*)d_in[2];
    const float* qkv_b  = (const float*)d_in[3];
    const float* kv_w   = (const float*)d_in[4];
    const float* kv_b   = (const float*)d_in[5];
    const float* qn_w   = (const float*)d_in[6];
    const float* kn_w   = (const float*)d_in[7];
    const float* proj_w = (const float*)d_in[8];
    const float* proj_b = (const float*)d_in[9];
    float* out = (float*)d_out;

    (void)in_sizes; (void)n_in; (void)out_size;

    cudaFuncSetAttribute(gemm_mma<false>, cudaFuncAttributeMaxDynamicSharedMemorySize, GEMM_SMEM);
    cudaFuncSetAttribute(gemm_mma<true>,  cudaFuncAttributeMaxDynamicSharedMemorySize, GEMM_SMEM);
    cudaFuncSetAttribute(attn_mma, cudaFuncAttributeMaxDynamicSharedMemorySize, ATTN_SMEM);

    // 1) merged fp32->fp16 conversion pass (8 floats/thread)
    cvt_all<<<CVT_BLOCKS, 256>>>(x, y, qkv_w, kv_w, proj_w);

    // 2) merged QKV (y 0..15) + KV (y 16..17) projections, fused RMSNorm
    gemm_mma<false><<<dim3(24, 18), 256, GEMM_SMEM>>>(qkv_b, kv_b, qn_w, kn_w, nullptr);

    // 3) attention (interleaved softmax/PV)
    attn_mma<<<dim3(NN / 128, HH, BB), 256, ATTN_SMEM>>>();

    // 4) output projection -> d_out
    gemm_mma<true><<<dim3(8, 16), 256, GEMM_SMEM>>>(proj_b, nullptr, nullptr, nullptr, out);
}